// round 4
// baseline (speedup 1.0000x reference)
#include <cuda_runtime.h>
#include <cuda_bf16.h>
#include <math.h>

#define N_NODES 8192
#define IN_DIM  512
#define H_DIM   128
#define MASK_WPR (N_NODES / 32)   // 256 mask words per row

// Scratch (allocation-free: __device__ globals)
__device__ __nv_bfloat16 g_Whb [(size_t)N_NODES * H_DIM];   // 2 MB bf16 (MMA B)
__device__ float         g_s   [N_NODES];
__device__ float         g_inv [N_NODES];
__device__ unsigned      g_mask[(size_t)N_NODES * MASK_WPR]; // 8 MB bitmask

// ---------------------------------------------------------------------------
// Kernel 1: Wh = h @ W^T + b  (bf16 out) + fused s = Wh @ a epilogue
// BM=32 -> grid=256 (full chip)
// ---------------------------------------------------------------------------
__global__ __launch_bounds__(256) void k_gemm_wh(const float* __restrict__ h,
                                                 const float* __restrict__ W,
                                                 const float* __restrict__ b,
                                                 const float* __restrict__ a) {
    __shared__ float hs[32][33];
    __shared__ float ws[128][33];
    __shared__ float sa[128];
    const int m0 = blockIdx.x * 32;
    const int t  = threadIdx.x;
    const int tm = t >> 4;     // 0..15 -> rows tm*2+v
    const int tn = t & 15;     // 0..15 -> cols tn+16u
    if (t < 128) sa[t] = a[t];

    float acc[2][8];
#pragma unroll
    for (int v = 0; v < 2; v++)
#pragma unroll
        for (int u = 0; u < 8; u++) acc[v][u] = 0.f;

    for (int k0 = 0; k0 < IN_DIM; k0 += 32) {
#pragma unroll
        for (int p = 0; p < 4; p++) {            // 32x32 h tile
            int idx = t + p * 256;
            int r = idx >> 5, c = idx & 31;
            hs[r][c] = h[(size_t)(m0 + r) * IN_DIM + k0 + c];
        }
#pragma unroll
        for (int p = 0; p < 16; p++) {           // 128x32 W tile
            int idx = t + p * 256;
            int r = idx >> 5, c = idx & 31;
            ws[r][c] = W[(size_t)r * IN_DIM + k0 + c];
        }
        __syncthreads();
#pragma unroll
        for (int k = 0; k < 32; k++) {
            float av[2], bv[8];
#pragma unroll
            for (int v = 0; v < 2; v++) av[v] = hs[tm * 2 + v][k];
#pragma unroll
            for (int u = 0; u < 8; u++) bv[u] = ws[tn + 16 * u][k];
#pragma unroll
            for (int v = 0; v < 2; v++)
#pragma unroll
                for (int u = 0; u < 8; u++)
                    acc[v][u] += av[v] * bv[u];
        }
        __syncthreads();
    }
    // epilogue: bf16 store + fused s = Wh @ a
#pragma unroll
    for (int v = 0; v < 2; v++) {
        int i = m0 + tm * 2 + v;
        float sdot = 0.f;
#pragma unroll
        for (int u = 0; u < 8; u++) {
            int hd = tn + 16 * u;
            float val = acc[v][u] + b[hd];
            g_Whb[(size_t)i * H_DIM + hd] = __float2bfloat16(val);
            sdot += val * sa[hd];
        }
#pragma unroll
        for (int o = 8; o; o >>= 1)
            sdot += __shfl_xor_sync(0xffffffffu, sdot, o);
        if (tn == 0) g_s[i] = sdot;
    }
}

// ---------------------------------------------------------------------------
// Kernel 2: per-row denom + bitmask compression.  One CTA per row.
// Mask layout (per 128-col group, 4 words): word w bit l  <->  col 4*l + w
// (matches the consumer's lane mapping exactly)
// ---------------------------------------------------------------------------
__global__ __launch_bounds__(256) void k_denom(const float* __restrict__ adj) {
    const int i    = blockIdx.x;
    const int t    = threadIdx.x;
    const int lane = t & 31;
    const int wid  = t >> 5;

    const float si = __ldg(&g_s[i]);
    const float4* __restrict__ row4 = (const float4*)(adj + (size_t)i * N_NODES);
    const float4* __restrict__ s4   = (const float4*)g_s;
    uint4* __restrict__ mrow = (uint4*)(g_mask + (size_t)i * MASK_WPR);

    float dsum = 0.f;
#pragma unroll
    for (int step = 0; step < 8; step++) {
        int grp = wid * 8 + step;             // 128-col group, 0..63
        int c4  = grp * 32 + lane;            // float4 index
        float4 a4 = __ldcs(&row4[c4]);
        float4 sj = __ldg(&s4[c4]);
        unsigned nib = (a4.x != 0.f) | ((a4.y != 0.f) << 1)
                     | ((a4.z != 0.f) << 2) | ((a4.w != 0.f) << 3);
        unsigned b0 = __ballot_sync(0xffffffffu, nib & 1u);
        unsigned b1 = __ballot_sync(0xffffffffu, nib & 2u);
        unsigned b2 = __ballot_sync(0xffffffffu, nib & 4u);
        unsigned b3 = __ballot_sync(0xffffffffu, nib & 8u);
        if (lane == 0) mrow[grp] = make_uint4(b0, b1, b2, b3);

        float x0 = si + sj.x, x1 = si + sj.y, x2 = si + sj.z, x3 = si + sj.w;
        x0 = x0 > 0.f ? x0 : 0.2f * x0;
        x1 = x1 > 0.f ? x1 : 0.2f * x1;
        x2 = x2 > 0.f ? x2 : 0.2f * x2;
        x3 = x3 > 0.f ? x3 : 0.2f * x3;
        if (a4.x != 0.f) dsum += __expf(x0);
        if (a4.y != 0.f) dsum += __expf(x1);
        if (a4.z != 0.f) dsum += __expf(x2);
        if (a4.w != 0.f) dsum += __expf(x3);
    }
#pragma unroll
    for (int o = 16; o; o >>= 1) dsum += __shfl_xor_sync(0xffffffffu, dsum, o);
    __shared__ float red[8];
    if (lane == 0) red[wid] = dsum;
    __syncthreads();
    if (t == 0) {
        float tot = 0.f;
#pragma unroll
        for (int w = 0; w < 8; w++) tot += red[w];
        g_inv[i] = (tot > 0.f) ? 1.f / tot : 0.f;
    }
}

// ---------------------------------------------------------------------------
// Kernel 3 (fused): alpha from bitmask (no adj re-read) + bf16 MMA -> z
// ---------------------------------------------------------------------------
#define RT 32
#define CT 128
#define APAD 136
#define ROWB (APAD * 2)
#define AS_BYTES (RT * APAD * 2)
#define BS_BYTES (CT * APAD * 2)
#define SMEM_TOTAL (AS_BYTES + 2 * BS_BYTES + 2 * RT * 4)

__device__ __forceinline__ void mma16816(float* c, const unsigned* a,
                                         unsigned b0, unsigned b1) {
    asm volatile(
        "mma.sync.aligned.m16n8k16.row.col.f32.bf16.bf16.f32 "
        "{%0,%1,%2,%3}, {%4,%5,%6,%7}, {%8,%9}, {%0,%1,%2,%3};"
        : "+f"(c[0]), "+f"(c[1]), "+f"(c[2]), "+f"(c[3])
        : "r"(a[0]), "r"(a[1]), "r"(a[2]), "r"(a[3]), "r"(b0), "r"(b1));
}

__device__ __forceinline__ void cp16(unsigned dst, const void* src) {
    asm volatile("cp.async.cg.shared.global [%0], [%1], 16;\n"
                 :: "r"(dst), "l"(src));
}

__global__ __launch_bounds__(256) void k_fused(float* __restrict__ z_out,
                                               float* __restrict__ alpha_out) {
    extern __shared__ char smem[];
    __nv_bfloat16* As = (__nv_bfloat16*)smem;
    __nv_bfloat16* Bs = (__nv_bfloat16*)(smem + AS_BYTES);
    float* sloc = (float*)(smem + AS_BYTES + 2 * BS_BYTES);
    float* invl = sloc + RT;

    const int t    = threadIdx.x;
    const int lane = t & 31;
    const int wid  = t >> 5;
    const int i0   = blockIdx.x * RT;

    if (t < RT) {
        sloc[t] = g_s[i0 + t];
        invl[t] = g_inv[i0 + t];
    }

    const unsigned as_base = (unsigned)__cvta_generic_to_shared(As);
    const unsigned bs_base = (unsigned)__cvta_generic_to_shared(Bs);

    // prologue: Wh chunk 0 via cp.async
#pragma unroll
    for (int p = 0; p < 8; p++) {
        int idx = t + p * 256;
        int jr = idx >> 4, u = idx & 15;
        cp16(bs_base + jr * ROWB + u * 16, (const char*)g_Whb + idx * 16);
    }
    asm volatile("cp.async.commit_group;");
    __syncthreads();

    const int wm = wid >> 2;
    const int wn = wid & 3;
    float acc[4][4];
#pragma unroll
    for (int n = 0; n < 4; n++)
#pragma unroll
        for (int c = 0; c < 4; c++) acc[n][c] = 0.f;

    const unsigned a_addr0 = as_base + (wm * 16 + (lane & 15)) * ROWB
                                     + ((lane >> 4) * 8) * 2;
    const unsigned b_rowsel = (lane & 15);
    const unsigned b_colsel = (lane >> 4) * 8;
    const float4* s4g = (const float4*)g_s;
    const uint4*  m4g = (const uint4*)g_mask;

    for (int c = 0; c < N_NODES / CT; c++) {
        const int j0  = c * CT;
        const int buf = c & 1;

        // ---- phase 1: alpha tile from bitmask ----
#pragma unroll
        for (int p = 0; p < 4; p++) {
            int r = wid + p * 8;                    // 0..31
            uint4 mw  = __ldg(&m4g[(size_t)(i0 + r) * (MASK_WPR / 4) + c]);
            float4 sj = __ldg(&s4g[c * (CT / 4) + lane]);
            float si = sloc[r], inv = invl[r];
            float4 ex;
            {
                float x = si + sj.x; x = x > 0.f ? x : 0.2f * x;
                ex.x = ((mw.x >> lane) & 1u) ? __expf(x) * inv : 0.f;
            }
            {
                float x = si + sj.y; x = x > 0.f ? x : 0.2f * x;
                ex.y = ((mw.y >> lane) & 1u) ? __expf(x) * inv : 0.f;
            }
            {
                float x = si + sj.z; x = x > 0.f ? x : 0.2f * x;
                ex.z = ((mw.z >> lane) & 1u) ? __expf(x) * inv : 0.f;
            }
            {
                float x = si + sj.w; x = x > 0.f ? x : 0.2f * x;
                ex.w = ((mw.w >> lane) & 1u) ? __expf(x) * inv : 0.f;
            }
            __stcs((float4*)(alpha_out + (size_t)(i0 + r) * N_NODES + j0) + lane, ex);
            __nv_bfloat162* dst = (__nv_bfloat162*)&As[r * APAD + lane * 4];
            dst[0] = __float22bfloat162_rn(make_float2(ex.x, ex.y));
            dst[1] = __float22bfloat162_rn(make_float2(ex.z, ex.w));
        }

        // prefetch next Wh chunk into other buffer
        if (c + 1 < N_NODES / CT) {
            const char* src = (const char*)(g_Whb + (size_t)(j0 + CT) * H_DIM);
            const unsigned bdst = bs_base + (buf ^ 1) * BS_BYTES;
#pragma unroll
            for (int p = 0; p < 8; p++) {
                int idx = t + p * 256;
                int jr = idx >> 4, u = idx & 15;
                cp16(bdst + jr * ROWB + u * 16, src + idx * 16);
            }
            asm volatile("cp.async.commit_group;");
            asm volatile("cp.async.wait_group 1;");
        } else {
            asm volatile("cp.async.wait_group 0;");
        }
        __syncthreads();

        // ---- phase 2: MMA ----
        const unsigned bbuf = bs_base + buf * BS_BYTES;
#pragma unroll
        for (int kk = 0; kk < CT; kk += 16) {
            unsigned a[4];
            asm volatile(
                "ldmatrix.sync.aligned.m8n8.x4.shared.b16 {%0,%1,%2,%3}, [%4];"
                : "=r"(a[0]), "=r"(a[1]), "=r"(a[2]), "=r"(a[3])
                : "r"(a_addr0 + kk * 2));
#pragma unroll
            for (int half = 0; half < 2; half++) {
                int n0 = wn * 32 + half * 16;
                unsigned baddr = bbuf + (kk + b_rowsel) * ROWB
                                      + (n0 + b_colsel) * 2;
                unsigned b[4];
                asm volatile(
                    "ldmatrix.sync.aligned.m8n8.x4.trans.shared.b16 "
                    "{%0,%1,%2,%3}, [%4];"
                    : "=r"(b[0]), "=r"(b[1]), "=r"(b[2]), "=r"(b[3])
                    : "r"(baddr));
                mma16816(acc[half * 2 + 0], a, b[0], b[1]);
                mma16816(acc[half * 2 + 1], a, b[2], b[3]);
            }
        }
        __syncthreads();
    }

    // ---- epilogue: z = sigmoid(acc) ----
    const int g = lane >> 2, q = lane & 3;
    const size_t r0 = (size_t)(i0 + wm * 16 + g) * H_DIM;
    const size_t r1 = r0 + 8 * H_DIM;
#pragma unroll
    for (int nt = 0; nt < 4; nt++) {
        int col = wn * 32 + nt * 8 + 2 * q;
        z_out[r0 + col]     = 1.f / (1.f + __expf(-acc[nt][0]));
        z_out[r0 + col + 1] = 1.f / (1.f + __expf(-acc[nt][1]));
        z_out[r1 + col]     = 1.f / (1.f + __expf(-acc[nt][2]));
        z_out[r1 + col + 1] = 1.f / (1.f + __expf(-acc[nt][3]));
    }
}

// ---------------------------------------------------------------------------
extern "C" void kernel_launch(void* const* d_in, const int* in_sizes, int n_in,
                              void* d_out, int out_size) {
    const float* h   = (const float*)d_in[0];  // (8192, 512)
    const float* adj = (const float*)d_in[1];  // (8192, 8192)
    const float* W   = (const float*)d_in[2];  // (128, 512)
    const float* b   = (const float*)d_in[3];  // (128,)
    const float* a   = (const float*)d_in[4];  // (1, 128)

    float* z_out     = (float*)d_out;
    float* alpha_out = z_out + (size_t)N_NODES * H_DIM;

    k_gemm_wh<<<N_NODES / 32, 256>>>(h, W, b, a);
    k_denom<<<N_NODES, 256>>>(adj);

    cudaFuncSetAttribute(k_fused, cudaFuncAttributeMaxDynamicSharedMemorySize,
                         SMEM_TOTAL);
    k_fused<<<N_NODES / RT, 256, SMEM_TOTAL>>>(z_out, alpha_out);
}